// round 16
// baseline (speedup 1.0000x reference)
#include <cuda_runtime.h>
#include <cuda_fp16.h>

// ---------------------------------------------------------------------------
// GAT (2 layers, edge features, H=2 heads x C=16) + mean pool + MLP -> [G,2]
// hist -> single-launch lookback scan -> FUSED (scatter || transform1, blocks
// proportionally interleaved so both roles stay co-resident) -> atomic-free
// warp-per-node agg (fp16 rows, 4 edges/iter) with layer-2 transform fused
// into agg0 and mean-pool fused into agg1.
// ---------------------------------------------------------------------------

#define MAXN 100352
#define MAXE 3211264
#define MAXG 256
#define NBS ((MAXN + 1023) / 1024)
#define SCB 1024                      // scatter blocks inside the fused kernel

__device__ __align__(16) uint2 g_h[MAXN * 8];       // layer-1 features, fp16x4
__device__ __align__(16) uint2 g_out[MAXN * 8];     // layer-2 features, fp16x4
__device__ __align__(16) float g_asrc[MAXN * 2];
__device__ __align__(16) float g_adst[MAXN * 2];
__device__ __align__(16) float g_asrc2[MAXN * 2];
__device__ __align__(16) float g_adst2[MAXN * 2];
__device__ __align__(16) int2  g_csr[MAXE];         // (src, ea_bits), dst-sorted
__device__ int g_rowptr[MAXN + 1];
__device__ int g_cursor[MAXN];
__device__ int g_deg[MAXN];                          // zero at load & in scan
__device__ volatile int g_flag[NBS];                 // lookback flags (0/1/2)
__device__ int g_aggval[NBS];
__device__ int g_incval[NBS];
__device__ __align__(16) float g_scal[8];            // [0]=esum(acc) [1]=mean [2..5]=ce
__device__ __align__(16) float g_pool[MAXG * 32];    // zero at load & in mlp
__device__ float g_cnt[MAXG];                        // zero at load & in mlp

__device__ __forceinline__ int clampi(int v, int hi) {
    return v < 0 ? 0 : (v >= hi ? hi - 1 : v);
}

// ---------------------------------------------------------------------------
// histogram + edge_attr sum (non-returning atomics -> RED, no wait)
__global__ void k_hist(const int* __restrict__ ei, const float* __restrict__ ea,
                       int E, int n) {
    __shared__ float red[512];
    float acc = 0.f;
    for (int e = blockIdx.x * 512 + threadIdx.x; e < E; e += gridDim.x * 512) {
        int d = clampi(ei[E + e], n);
        atomicAdd(&g_deg[d], 1);
        acc += ea[e];
    }
    red[threadIdx.x] = acc;
    __syncthreads();
    for (int s = 256; s; s >>= 1) {
        if (threadIdx.x < s) red[threadIdx.x] += red[threadIdx.x + s];
        __syncthreads();
    }
    if (threadIdx.x == 0) atomicAdd(&g_scal[0], red[0]);
}

// ---------------------------------------------------------------------------
// single-launch exclusive scan via decoupled lookback (<=98 blocks resident).
// Writes rowptr AND cursor; folds prep; re-zeroes deg.
__global__ void k_scanL(int n, int E,
                        const float* __restrict__ We1, const float* __restrict__ ae1,
                        const float* __restrict__ We2, const float* __restrict__ ae2) {
    __shared__ int sm[1024];
    __shared__ int s_excl;
    int t = threadIdx.x, b = blockIdx.x;

    if (b == 0) {                      // folded prep
        if (t == 32) g_scal[1] = g_scal[0] / (float)E;
        if (t >= 33 && t < 37) {
            int tt = t - 33;
            int layer = tt >> 1, hh = tt & 1;
            const float* We = layer ? We2 : We1;
            const float* ae = layer ? ae2 : ae1;
            float c = 0.f;
            for (int i = 0; i < 16; i++) c += We[hh * 16 + i] * ae[hh * 16 + i];
            g_scal[2 + layer * 2 + hh] = c;
        }
    }

    int i = b * 1024 + t;
    int v = (i < n) ? g_deg[i] : 0;
    int x = v;
    sm[t] = x;
    __syncthreads();
    #pragma unroll
    for (int off = 1; off < 1024; off <<= 1) {
        int y = (t >= off) ? sm[t - off] : 0;
        __syncthreads();
        x += y;
        sm[t] = x;
        __syncthreads();
    }

    if (t == 1023) {
        if (b == 0) {
            g_incval[0] = x;
            __threadfence();
            g_flag[0] = 2;
        } else {
            g_aggval[b] = x;
            __threadfence();
            g_flag[b] = 1;
        }
    }
    if (t == 0) {
        int excl = 0;
        if (b > 0) {
            int p = b - 1;
            while (true) {
                int f;
                do { f = g_flag[p]; } while (f == 0);
                __threadfence();
                if (f == 2) { excl += g_incval[p]; break; }
                excl += g_aggval[p];
                p--;
            }
            g_incval[b] = excl + sm[1023];
            __threadfence();
            g_flag[b] = 2;
        }
        s_excl = excl;
    }
    __syncthreads();
    if (i < n) {
        int r = s_excl + x - v;         // exclusive prefix
        g_rowptr[i] = r;
        g_cursor[i] = r;
        g_deg[i] = 0;                    // restore for next replay
    }
    if (b == 0 && t == 0) g_rowptr[n] = E;
}

// ---------------------------------------------------------------------------
// FUSED: transform1 (64 nodes/block) || 4x-unrolled cursor scatter.
// Block roles proportionally interleaved so both populations are co-resident:
// transform is L1/FMA-bound, scatter is L2-atomic-latency-bound (issue ~6%).
__global__ void __launch_bounds__(256)
k_fused(const float* __restrict__ xin, const float* __restrict__ W,
        const float* __restrict__ a_src, const float* __restrict__ a_dst,
        const int* __restrict__ ei, const float* __restrict__ ea,
        int n, int E, int tb, int total) {
    __shared__ float W_sh[128 * 32];                 // 16 KB
    __shared__ float4 x4_sh[64][33];                 // 33.8 KB (padded)
    __shared__ float s_as[32], s_ad[32];
    __shared__ float sm_ps[8][64], sm_pd[8][64];
    int tid = threadIdx.x;
    int b = blockIdx.x;

    int c1 = (int)(((long long)b * tb) / total);
    int c2 = (int)(((long long)(b + 1) * tb) / total);

    if (c2 == c1) {
        // ---------------- scatter role (block index sb = b - c1) ----------
        int sb = b - c1;
        if (sb == 0 && tid < NBS) g_flag[tid] = 0;   // reset lookback flags
        int t = sb * 256 + tid;
        int stride = SCB * 256;
        int Emain = E & ~3;
        for (int base = t * 4; base < Emain; base += stride * 4) {
            int s0 = clampi(ei[base],     n), d0 = clampi(ei[E + base],     n);
            int s1 = clampi(ei[base + 1], n), d1 = clampi(ei[E + base + 1], n);
            int s2 = clampi(ei[base + 2], n), d2 = clampi(ei[E + base + 2], n);
            int s3 = clampi(ei[base + 3], n), d3 = clampi(ei[E + base + 3], n);
            float a0 = ea[base], a1 = ea[base + 1], a2 = ea[base + 2], a3 = ea[base + 3];
            int p0 = atomicAdd(&g_cursor[d0], 1);
            int p1 = atomicAdd(&g_cursor[d1], 1);
            int p2 = atomicAdd(&g_cursor[d2], 1);
            int p3 = atomicAdd(&g_cursor[d3], 1);
            g_csr[p0] = make_int2(s0, __float_as_int(a0));
            g_csr[p1] = make_int2(s1, __float_as_int(a1));
            g_csr[p2] = make_int2(s2, __float_as_int(a2));
            g_csr[p3] = make_int2(s3, __float_as_int(a3));
        }
        int r = E - Emain;
        if (t < r) {                                  // tail, exactly once
            int e = Emain + t;
            int s = clampi(ei[e], n);
            int d = clampi(ei[E + e], n);
            int p = atomicAdd(&g_cursor[d], 1);
            g_csr[p] = make_int2(s, __float_as_int(ea[e]));
        }
        return;
    }

    // ---------------- transform role (block index c1; 64 nodes) -----------
    for (int i = tid; i < 128 * 32; i += 256) W_sh[i] = W[i];
    if (tid < 32) {
        s_as[tid] = a_src[tid];
        s_ad[tid] = a_dst[tid];
    }
    __syncthreads();
    int nb = c1 * 64;
    for (int i = tid; i < 64 * 32; i += 256) {
        int r = i >> 5, c4 = i & 31;
        int node = nb + r;
        float4 v = make_float4(0.f, 0.f, 0.f, 0.f);
        if (node < n)
            v = ((const float4*)(xin + (size_t)node * 128))[c4];
        x4_sh[r][c4] = v;
    }
    __syncthreads();

    int w = tid >> 5, lane = tid & 31;
    int node0 = nb + lane, node1 = nb + 32 + lane;
    float4 ac0 = make_float4(0.f, 0.f, 0.f, 0.f);
    float4 ac1 = make_float4(0.f, 0.f, 0.f, 0.f);
    const float4* W4 = (const float4*)W_sh;
    #pragma unroll 4
    for (int kq = 0; kq < 32; kq++) {
        float4 x0 = x4_sh[lane][kq];                 // LDS.128 conflict-free
        float4 x1 = x4_sh[lane + 32][kq];
        float4 w0 = W4[(kq * 4 + 0) * 8 + w];        // broadcast LDS.128 x4
        float4 w1 = W4[(kq * 4 + 1) * 8 + w];
        float4 w2 = W4[(kq * 4 + 2) * 8 + w];
        float4 w3 = W4[(kq * 4 + 3) * 8 + w];
        ac0.x = fmaf(x0.x, w0.x, ac0.x); ac0.y = fmaf(x0.x, w0.y, ac0.y);
        ac0.z = fmaf(x0.x, w0.z, ac0.z); ac0.w = fmaf(x0.x, w0.w, ac0.w);
        ac0.x = fmaf(x0.y, w1.x, ac0.x); ac0.y = fmaf(x0.y, w1.y, ac0.y);
        ac0.z = fmaf(x0.y, w1.z, ac0.z); ac0.w = fmaf(x0.y, w1.w, ac0.w);
        ac0.x = fmaf(x0.z, w2.x, ac0.x); ac0.y = fmaf(x0.z, w2.y, ac0.y);
        ac0.z = fmaf(x0.z, w2.z, ac0.z); ac0.w = fmaf(x0.z, w2.w, ac0.w);
        ac0.x = fmaf(x0.w, w3.x, ac0.x); ac0.y = fmaf(x0.w, w3.y, ac0.y);
        ac0.z = fmaf(x0.w, w3.z, ac0.z); ac0.w = fmaf(x0.w, w3.w, ac0.w);
        ac1.x = fmaf(x1.x, w0.x, ac1.x); ac1.y = fmaf(x1.x, w0.y, ac1.y);
        ac1.z = fmaf(x1.x, w0.z, ac1.z); ac1.w = fmaf(x1.x, w0.w, ac1.w);
        ac1.x = fmaf(x1.y, w1.x, ac1.x); ac1.y = fmaf(x1.y, w1.y, ac1.y);
        ac1.z = fmaf(x1.y, w1.z, ac1.z); ac1.w = fmaf(x1.y, w1.w, ac1.w);
        ac1.x = fmaf(x1.z, w2.x, ac1.x); ac1.y = fmaf(x1.z, w2.y, ac1.y);
        ac1.z = fmaf(x1.z, w2.z, ac1.z); ac1.w = fmaf(x1.z, w2.w, ac1.w);
        ac1.x = fmaf(x1.w, w3.x, ac1.x); ac1.y = fmaf(x1.w, w3.y, ac1.y);
        ac1.z = fmaf(x1.w, w3.z, ac1.z); ac1.w = fmaf(x1.w, w3.w, ac1.w);
    }
    if (node0 < n) {
        union { __half2 h[2]; uint2 u; } pk;
        pk.h[0] = __floats2half2_rn(ac0.x, ac0.y);
        pk.h[1] = __floats2half2_rn(ac0.z, ac0.w);
        g_h[node0 * 8 + w] = pk.u;
    }
    if (node1 < n) {
        union { __half2 h[2]; uint2 u; } pk;
        pk.h[0] = __floats2half2_rn(ac1.x, ac1.y);
        pk.h[1] = __floats2half2_rn(ac1.z, ac1.w);
        g_h[node1 * 8 + w] = pk.u;
    }

    sm_ps[w][lane]      = ac0.x * s_as[w * 4]     + ac0.y * s_as[w * 4 + 1]
                        + ac0.z * s_as[w * 4 + 2] + ac0.w * s_as[w * 4 + 3];
    sm_pd[w][lane]      = ac0.x * s_ad[w * 4]     + ac0.y * s_ad[w * 4 + 1]
                        + ac0.z * s_ad[w * 4 + 2] + ac0.w * s_ad[w * 4 + 3];
    sm_ps[w][lane + 32] = ac1.x * s_as[w * 4]     + ac1.y * s_as[w * 4 + 1]
                        + ac1.z * s_as[w * 4 + 2] + ac1.w * s_as[w * 4 + 3];
    sm_pd[w][lane + 32] = ac1.x * s_ad[w * 4]     + ac1.y * s_ad[w * 4 + 1]
                        + ac1.z * s_ad[w * 4 + 2] + ac1.w * s_ad[w * 4 + 3];
    __syncthreads();
    if (tid < 128) {
        int l = tid & 63, hh = tid >> 6;
        int node2 = nb + l;
        if (node2 < n) {
            int wb = hh * 4;
            float vs = sm_ps[wb][l] + sm_ps[wb + 1][l] + sm_ps[wb + 2][l] + sm_ps[wb + 3][l];
            float vd = sm_pd[wb][l] + sm_pd[wb + 1][l] + sm_pd[wb + 2][l] + sm_pd[wb + 3][l];
            g_asrc[node2 * 2 + hh] = vs;
            g_adst[node2 * 2 + hh] = vd;
        }
    }
}

// ---------------------------------------------------------------------------
// fused aggregation: warp per dst node; 4 edges per gather iteration
// (four 8-lane groups); fp16 feature rows decoded to fp32 for accumulation.
// LAYER==0: features g_h/asrc/adst; epilogue = layer-2 transform -> g_out.
// LAYER==1: features g_out/asrc2/adst2; epilogue = mean-pool accumulation.
template <int LAYER>
__global__ void __launch_bounds__(256, 6)
k_agg(int n,
      const float* __restrict__ W2, const float* __restrict__ b1,
      const float* __restrict__ as2, const float* __restrict__ ad2,
      const int* __restrict__ batch, const float* __restrict__ b2,
      int G) {
    __shared__ float4 stage[8][32];
    __shared__ float W2s[32 * 32];
    __shared__ float b1s[32], as2s[32], ad2s[32];
    int tid = threadIdx.x;
    if (LAYER == 0) {
        for (int i = tid; i < 1024; i += 256) W2s[i] = W2[i];
        if (tid < 32) {
            b1s[tid] = b1[tid];
            as2s[tid] = as2[tid];
            ad2s[tid] = ad2[tid];
        }
        __syncthreads();
    }

    int wg = (blockIdx.x * blockDim.x + tid) >> 5;
    if (wg >= n) return;
    int w = tid >> 5, lane = tid & 31;
    int grp = lane >> 3;           // 4 groups of 8 lanes; group g takes edge t+g
    int q = lane & 7;              // lane-in-group owns columns 4q..4q+3
    int node = wg;
    float c0 = g_scal[2 + LAYER * 2];
    float c1 = g_scal[3 + LAYER * 2];
    float mean = g_scal[1];
    const uint2*  hf8  = LAYER ? g_out   : g_h;
    const float*  asrc = LAYER ? g_asrc2 : g_asrc;
    const float*  adst = LAYER ? g_adst2 : g_adst;
    float2 ad = ((const float2*)adst)[node];
    bool head1 = q >= 4;           // column quad's head (cols 16..31 -> head 1)

    float4 acc = make_float4(0.f, 0.f, 0.f, 0.f);
    float s0 = 0.f, s1 = 0.f;
    int beg = g_rowptr[node], end = g_rowptr[node + 1];

    for (int j0 = beg; j0 < end; j0 += 32) {
        int j = j0 + lane;
        bool v = j < end;
        int src = node;
        float av = 0.f;
        if (v) {
            int2 p = g_csr[j];
            src = p.x;
            av = __int_as_float(p.y);
        }
        float2 as = ((const float2*)asrc)[src];
        float a0 = as.x + ad.x + av * c0;
        float a1 = as.y + ad.y + av * c1;
        a0 = a0 > 0.f ? a0 : 0.2f * a0;
        a1 = a1 > 0.f ? a1 : 0.2f * a1;
        float ex0 = v ? __expf(a0) : 0.f;   // invalid lanes stage ex=0
        float ex1 = v ? __expf(a1) : 0.f;
        s0 += ex0;
        s1 += ex1;
        stage[w][lane] = make_float4(__int_as_float(src), ex0, ex1, 0.f);
        __syncwarp();
        int cnt = min(end - j0, 32);
        if (cnt == 32) {
            #pragma unroll
            for (int t = 0; t < 32; t += 4) {
                float4 p = stage[w][t + grp];
                union { uint2 u; __half2 h[2]; } pk;
                pk.u = hf8[__float_as_int(p.x) * 8 + q];   // 64B row per edge
                float2 f01 = __half22float2(pk.h[0]);
                float2 f23 = __half22float2(pk.h[1]);
                float e = head1 ? p.z : p.y;
                acc.x = fmaf(f01.x, e, acc.x);
                acc.y = fmaf(f01.y, e, acc.y);
                acc.z = fmaf(f23.x, e, acc.z);
                acc.w = fmaf(f23.y, e, acc.w);
            }
        } else {
            for (int t = 0; t < cnt; t += 4) {            // slots >= cnt carry ex=0
                float4 p = stage[w][t + grp];
                union { uint2 u; __half2 h[2]; } pk;
                pk.u = hf8[__float_as_int(p.x) * 8 + q];
                float2 f01 = __half22float2(pk.h[0]);
                float2 f23 = __half22float2(pk.h[1]);
                float e = head1 ? p.z : p.y;
                acc.x = fmaf(f01.x, e, acc.x);
                acc.y = fmaf(f01.y, e, acc.y);
                acc.z = fmaf(f23.x, e, acc.z);
                acc.w = fmaf(f23.y, e, acc.w);
            }
        }
        __syncwarp();
    }

    // combine the 4 groups (lanes q, q+8, q+16, q+24 hold the same columns)
    acc.x += __shfl_down_sync(0xffffffffu, acc.x, 16);
    acc.y += __shfl_down_sync(0xffffffffu, acc.y, 16);
    acc.z += __shfl_down_sync(0xffffffffu, acc.z, 16);
    acc.w += __shfl_down_sync(0xffffffffu, acc.w, 16);
    acc.x += __shfl_down_sync(0xffffffffu, acc.x, 8);
    acc.y += __shfl_down_sync(0xffffffffu, acc.y, 8);
    acc.z += __shfl_down_sync(0xffffffffu, acc.z, 8);
    acc.w += __shfl_down_sync(0xffffffffu, acc.w, 8);

    // self loop (src = node, ea = mean): add in lanes 0-7 after combine
    {
        float2 as = ((const float2*)asrc)[node];
        float a0 = as.x + ad.x + mean * c0;
        float a1 = as.y + ad.y + mean * c1;
        a0 = a0 > 0.f ? a0 : 0.2f * a0;
        a1 = a1 > 0.f ? a1 : 0.2f * a1;
        float ex0 = __expf(a0), ex1 = __expf(a1);
        if (lane == 0) { s0 += ex0; s1 += ex1; }
        union { uint2 u; __half2 h[2]; } pk;
        pk.u = hf8[node * 8 + q];
        float2 f01 = __half22float2(pk.h[0]);
        float2 f23 = __half22float2(pk.h[1]);
        float e = (lane < 8) ? (head1 ? ex1 : ex0) : 0.f;
        acc.x = fmaf(f01.x, e, acc.x);
        acc.y = fmaf(f01.y, e, acc.y);
        acc.z = fmaf(f23.x, e, acc.z);
        acc.w = fmaf(f23.y, e, acc.w);
    }

    #pragma unroll
    for (int off = 16; off; off >>= 1) {
        s0 += __shfl_xor_sync(0xffffffffu, s0, off);
        s1 += __shfl_xor_sync(0xffffffffu, s1, off);
    }
    float sinv = 1.f / ((head1 ? s1 : s0) + 1e-16f);
    float4 o4 = make_float4(acc.x * sinv, acc.y * sinv, acc.z * sinv, acc.w * sinv);
    // o4 valid in lanes 0-7 (columns 4q..4q+3)

    if (LAYER == 0) {
        // fused layer-2 transform: x2 = relu(o + b1); h2 = x2 @ W2 (fp32 math)
        float* xrow = (float*)&stage[w][0];
        if (lane < 8) {
            xrow[4 * q]     = fmaxf(o4.x + b1s[4 * q], 0.f);
            xrow[4 * q + 1] = fmaxf(o4.y + b1s[4 * q + 1], 0.f);
            xrow[4 * q + 2] = fmaxf(o4.z + b1s[4 * q + 2], 0.f);
            xrow[4 * q + 3] = fmaxf(o4.w + b1s[4 * q + 3], 0.f);
        }
        __syncwarp();
        float acc2 = 0.f;
        #pragma unroll 8
        for (int k = 0; k < 32; k++)
            acc2 = fmaf(xrow[k], W2s[k * 32 + lane], acc2);
        // store h2 row as fp16 (pairs from even lanes)
        float nbv = __shfl_down_sync(0xffffffffu, acc2, 1);
        if ((lane & 1) == 0) {
            __half2 hv = __floats2half2_rn(acc2, nbv);
            ((unsigned*)g_out)[node * 16 + (lane >> 1)] = *(unsigned*)&hv;
        }
        float ps = acc2 * as2s[lane];
        float pd = acc2 * ad2s[lane];
        #pragma unroll
        for (int off = 8; off; off >>= 1) {
            ps += __shfl_down_sync(0xffffffffu, ps, off, 16);
            pd += __shfl_down_sync(0xffffffffu, pd, off, 16);
        }
        if ((lane & 15) == 0) {
            int hh = lane >> 4;
            g_asrc2[node * 2 + hh] = ps;
            g_adst2[node * 2 + hh] = pd;
        }
    } else {
        int g = clampi(batch[node], G);
        if (lane < 8) {
            float4 add = make_float4(o4.x + b2[4 * q],     o4.y + b2[4 * q + 1],
                                     o4.z + b2[4 * q + 2], o4.w + b2[4 * q + 3]);
            atomicAdd((float4*)&g_pool[g * 32 + 4 * q], add);
        }
        if (lane == 0) atomicAdd(&g_cnt[g], 1.f);
    }
}

// ---------------------------------------------------------------------------
// MLP head + accumulator cleanup for the next pipeline pass.
__global__ void k_mlp(float* __restrict__ out,
                      const float* __restrict__ Wf1, const float* __restrict__ bf1,
                      const float* __restrict__ Wf2, const float* __restrict__ bf2, int G) {
    int g = blockIdx.x * blockDim.x + threadIdx.x;
    if (g >= G) return;
    float cnt = g_cnt[g];
    float inv = 1.f / fmaxf(cnt, 1.f);
    float emb[32];
    #pragma unroll
    for (int i = 0; i < 32; i++) {
        emb[i] = g_pool[g * 32 + i] * inv;
        g_pool[g * 32 + i] = 0.f;        // restore for next replay
    }
    g_cnt[g] = 0.f;
    if (g == 0) g_scal[0] = 0.f;
    float o0 = bf2[0], o1 = bf2[1];
    for (int j = 0; j < 32; j++) {
        float z = bf1[j];
        #pragma unroll
        for (int i = 0; i < 32; i++) z = fmaf(emb[i], Wf1[i * 32 + j], z);
        z = fmaxf(z, 0.f);
        o0 = fmaf(z, Wf2[j * 2], o0);
        o1 = fmaf(z, Wf2[j * 2 + 1], o1);
    }
    out[g * 2] = o0;
    out[g * 2 + 1] = o1;
}

// ---------------------------------------------------------------------------
extern "C" void kernel_launch(void* const* d_in, const int* in_sizes, int n_in,
                              void* d_out, int out_size) {
    const float* x     = (const float*)d_in[0];
    const int*   ei    = (const int*)d_in[1];
    const float* ea    = (const float*)d_in[2];
    const int*   batch = (const int*)d_in[3];
    const float* W1  = (const float*)d_in[4];
    const float* as1 = (const float*)d_in[5];
    const float* ad1 = (const float*)d_in[6];
    const float* We1 = (const float*)d_in[7];
    const float* ae1 = (const float*)d_in[8];
    const float* b1  = (const float*)d_in[9];
    const float* W2  = (const float*)d_in[10];
    const float* as2 = (const float*)d_in[11];
    const float* ad2 = (const float*)d_in[12];
    const float* We2 = (const float*)d_in[13];
    const float* ae2 = (const float*)d_in[14];
    const float* b2  = (const float*)d_in[15];
    const float* Wf1 = (const float*)d_in[16];
    const float* bf1 = (const float*)d_in[17];
    const float* Wf2 = (const float*)d_in[18];
    const float* bf2 = (const float*)d_in[19];

    int N = in_sizes[0] / 128;
    int E = in_sizes[1] / 2;
    int G = out_size / 2;
    int nb = (N + 1023) / 1024;
    int tb = (N + 63) / 64;           // transform blocks (64 nodes each)
    int total = tb + SCB;             // + scatter blocks, interleaved
    int ab = (N + 7) / 8;

    // 1: histogram + esum
    k_hist<<<2048, 512>>>(ei, ea, E, N);
    // 2: single-launch scan (rowptr + cursor, folded prep, deg re-zero)
    k_scanL<<<nb, 1024>>>(N, E, We1, ae1, We2, ae2);
    // 3: FUSED scatter || transform1 (proportionally interleaved roles)
    k_fused<<<total, 256>>>(x, W1, as1, ad1, ei, ea, N, E, tb, total);
    // 4: agg0 (fused layer-2 transform epilogue)  <- ncu capture slot
    k_agg<0><<<ab, 256>>>(N, W2, b1, as2, ad2, nullptr, nullptr, G);
    // 5: agg1 (fused mean-pool)
    k_agg<1><<<ab, 256>>>(N, nullptr, nullptr, nullptr, nullptr, batch, b2, G);
    // 6: MLP head (+ accumulator cleanup)
    k_mlp<<<1, 64>>>((float*)d_out, Wf1, bf1, Wf2, bf2, G);
}

// round 17
// speedup vs baseline: 1.0238x; 1.0238x over previous
#include <cuda_runtime.h>
#include <cuda_fp16.h>

// ---------------------------------------------------------------------------
// GAT (2 layers, edge features, H=2 heads x C=16) + mean pool + MLP -> [G,2]
// vectorized hist -> single-launch lookback scan -> 4x-unrolled cursor
// scatter -> 64-node transform1 (capture slot) -> atomic-free warp-per-node
// agg (fp16 rows, 4 edges/iter) with layer-2 transform fused into agg0 and
// mean-pool fused into agg1.
// ---------------------------------------------------------------------------

#define MAXN 100352
#define MAXE 3211264
#define MAXG 256
#define NBS ((MAXN + 1023) / 1024)

__device__ __align__(16) uint2 g_h[MAXN * 8];       // layer-1 features, fp16x4
__device__ __align__(16) uint2 g_out[MAXN * 8];     // layer-2 features, fp16x4
__device__ __align__(16) float g_asrc[MAXN * 2];
__device__ __align__(16) float g_adst[MAXN * 2];
__device__ __align__(16) float g_asrc2[MAXN * 2];
__device__ __align__(16) float g_adst2[MAXN * 2];
__device__ __align__(16) int2  g_csr[MAXE];         // (src, ea_bits), dst-sorted
__device__ int g_rowptr[MAXN + 1];
__device__ int g_cursor[MAXN];
__device__ int g_deg[MAXN];                          // zero at load & in scan
__device__ volatile int g_flag[NBS];                 // lookback flags (0/1/2)
__device__ int g_aggval[NBS];
__device__ int g_incval[NBS];
__device__ __align__(16) float g_scal[8];            // [0]=esum(acc) [1]=mean [2..5]=ce
__device__ __align__(16) float g_pool[MAXG * 32];    // zero at load & in mlp
__device__ float g_cnt[MAXG];                        // zero at load & in mlp

__device__ __forceinline__ int clampi(int v, int hi) {
    return v < 0 ? 0 : (v >= hi ? hi - 1 : v);
}

// ---------------------------------------------------------------------------
// histogram + edge_attr sum; vectorized int4/float4 path when E % 4 == 0
__global__ void k_hist(const int* __restrict__ ei, const float* __restrict__ ea,
                       int E, int n) {
    __shared__ float red[512];
    float acc = 0.f;
    int tid = blockIdx.x * 512 + threadIdx.x;
    int stride = gridDim.x * 512;
    if ((E & 3) == 0) {
        const int4*   d4 = (const int4*)(ei + E);
        const float4* a4 = (const float4*)ea;
        int Q = E >> 2;
        for (int q = tid; q < Q; q += stride) {
            int4 d = d4[q];
            float4 a = a4[q];
            atomicAdd(&g_deg[clampi(d.x, n)], 1);
            atomicAdd(&g_deg[clampi(d.y, n)], 1);
            atomicAdd(&g_deg[clampi(d.z, n)], 1);
            atomicAdd(&g_deg[clampi(d.w, n)], 1);
            acc += a.x + a.y + a.z + a.w;
        }
    } else {
        for (int e = tid; e < E; e += stride) {
            atomicAdd(&g_deg[clampi(ei[E + e], n)], 1);
            acc += ea[e];
        }
    }
    red[threadIdx.x] = acc;
    __syncthreads();
    for (int s = 256; s; s >>= 1) {
        if (threadIdx.x < s) red[threadIdx.x] += red[threadIdx.x + s];
        __syncthreads();
    }
    if (threadIdx.x == 0) atomicAdd(&g_scal[0], red[0]);
}

// ---------------------------------------------------------------------------
// single-launch exclusive scan via decoupled lookback (<=98 blocks resident).
// Writes rowptr AND cursor; folds prep; re-zeroes deg.
__global__ void k_scanL(int n, int E,
                        const float* __restrict__ We1, const float* __restrict__ ae1,
                        const float* __restrict__ We2, const float* __restrict__ ae2) {
    __shared__ int sm[1024];
    __shared__ int s_excl;
    int t = threadIdx.x, b = blockIdx.x;

    if (b == 0) {                      // folded prep
        if (t == 32) g_scal[1] = g_scal[0] / (float)E;
        if (t >= 33 && t < 37) {
            int tt = t - 33;
            int layer = tt >> 1, hh = tt & 1;
            const float* We = layer ? We2 : We1;
            const float* ae = layer ? ae2 : ae1;
            float c = 0.f;
            for (int i = 0; i < 16; i++) c += We[hh * 16 + i] * ae[hh * 16 + i];
            g_scal[2 + layer * 2 + hh] = c;
        }
    }

    int i = b * 1024 + t;
    int v = (i < n) ? g_deg[i] : 0;
    int x = v;
    sm[t] = x;
    __syncthreads();
    #pragma unroll
    for (int off = 1; off < 1024; off <<= 1) {
        int y = (t >= off) ? sm[t - off] : 0;
        __syncthreads();
        x += y;
        sm[t] = x;
        __syncthreads();
    }

    if (t == 1023) {
        if (b == 0) {
            g_incval[0] = x;
            __threadfence();
            g_flag[0] = 2;
        } else {
            g_aggval[b] = x;
            __threadfence();
            g_flag[b] = 1;
        }
    }
    if (t == 0) {
        int excl = 0;
        if (b > 0) {
            int p = b - 1;
            while (true) {
                int f;
                do { f = g_flag[p]; } while (f == 0);
                __threadfence();
                if (f == 2) { excl += g_incval[p]; break; }
                excl += g_aggval[p];
                p--;
            }
            g_incval[b] = excl + sm[1023];
            __threadfence();
            g_flag[b] = 2;
        }
        s_excl = excl;
    }
    __syncthreads();
    if (i < n) {
        int r = s_excl + x - v;         // exclusive prefix
        g_rowptr[i] = r;
        g_cursor[i] = r;
        g_deg[i] = 0;                    // restore for next replay
    }
    if (b == 0 && t == 0) g_rowptr[n] = E;
}

// ---------------------------------------------------------------------------
// cursor-atomic scatter, 4 edges per thread per iteration (independent
// atomics, MLP=4 on the L2-atomic latency). Resets lookback flags.
__global__ void k_scatter(const int* __restrict__ ei, const float* __restrict__ ea,
                          int E, int n) {
    if (blockIdx.x == 0 && threadIdx.x < NBS) g_flag[threadIdx.x] = 0;
    int tid = blockIdx.x * blockDim.x + threadIdx.x;
    int stride = gridDim.x * blockDim.x;
    int Emain = E & ~3;
    for (int base = tid * 4; base < Emain; base += stride * 4) {
        int s0 = clampi(ei[base],     n), d0 = clampi(ei[E + base],     n);
        int s1 = clampi(ei[base + 1], n), d1 = clampi(ei[E + base + 1], n);
        int s2 = clampi(ei[base + 2], n), d2 = clampi(ei[E + base + 2], n);
        int s3 = clampi(ei[base + 3], n), d3 = clampi(ei[E + base + 3], n);
        float a0 = ea[base], a1 = ea[base + 1], a2 = ea[base + 2], a3 = ea[base + 3];
        int p0 = atomicAdd(&g_cursor[d0], 1);
        int p1 = atomicAdd(&g_cursor[d1], 1);
        int p2 = atomicAdd(&g_cursor[d2], 1);
        int p3 = atomicAdd(&g_cursor[d3], 1);
        g_csr[p0] = make_int2(s0, __float_as_int(a0));
        g_csr[p1] = make_int2(s1, __float_as_int(a1));
        g_csr[p2] = make_int2(s2, __float_as_int(a2));
        g_csr[p3] = make_int2(s3, __float_as_int(a3));
    }
    int r = E - Emain;
    if (tid < r) {                                    // tail, exactly once
        int e = Emain + tid;
        int s = clampi(ei[e], n);
        int d = clampi(ei[E + e], n);
        int p = atomicAdd(&g_cursor[d], 1);
        g_csr[p] = make_int2(s, __float_as_int(ea[e]));
    }
}

// ---------------------------------------------------------------------------
// layer-1 transform, 64 nodes/block (2 per lane): per kq-step 6 LDS.128 feed
// 32 FMA-instructions (~40% fewer L1 wavefronts per FMA than 32-node form).
__global__ void __launch_bounds__(256)
k_transform1(const float* __restrict__ xin, const float* __restrict__ W,
             const float* __restrict__ a_src, const float* __restrict__ a_dst,
             int n) {
    __shared__ float W_sh[128 * 32];                 // 16 KB
    __shared__ float4 x4_sh[64][33];                 // 33.8 KB (padded)
    __shared__ float s_as[32], s_ad[32];
    __shared__ float sm_ps[8][64], sm_pd[8][64];
    int tid = threadIdx.x;
    for (int i = tid; i < 128 * 32; i += 256) W_sh[i] = W[i];
    if (tid < 32) {
        s_as[tid] = a_src[tid];
        s_ad[tid] = a_dst[tid];
    }
    __syncthreads();
    int nb = blockIdx.x * 64;
    for (int i = tid; i < 64 * 32; i += 256) {
        int r = i >> 5, c4 = i & 31;
        int node = nb + r;
        float4 v = make_float4(0.f, 0.f, 0.f, 0.f);
        if (node < n)
            v = ((const float4*)(xin + (size_t)node * 128))[c4];
        x4_sh[r][c4] = v;
    }
    __syncthreads();

    int w = tid >> 5, lane = tid & 31;
    int node0 = nb + lane, node1 = nb + 32 + lane;
    float4 ac0 = make_float4(0.f, 0.f, 0.f, 0.f);
    float4 ac1 = make_float4(0.f, 0.f, 0.f, 0.f);
    const float4* W4 = (const float4*)W_sh;
    #pragma unroll 4
    for (int kq = 0; kq < 32; kq++) {
        float4 x0 = x4_sh[lane][kq];                 // LDS.128 conflict-free
        float4 x1 = x4_sh[lane + 32][kq];
        float4 w0 = W4[(kq * 4 + 0) * 8 + w];        // broadcast LDS.128 x4
        float4 w1 = W4[(kq * 4 + 1) * 8 + w];
        float4 w2 = W4[(kq * 4 + 2) * 8 + w];
        float4 w3 = W4[(kq * 4 + 3) * 8 + w];
        ac0.x = fmaf(x0.x, w0.x, ac0.x); ac0.y = fmaf(x0.x, w0.y, ac0.y);
        ac0.z = fmaf(x0.x, w0.z, ac0.z); ac0.w = fmaf(x0.x, w0.w, ac0.w);
        ac0.x = fmaf(x0.y, w1.x, ac0.x); ac0.y = fmaf(x0.y, w1.y, ac0.y);
        ac0.z = fmaf(x0.y, w1.z, ac0.z); ac0.w = fmaf(x0.y, w1.w, ac0.w);
        ac0.x = fmaf(x0.z, w2.x, ac0.x); ac0.y = fmaf(x0.z, w2.y, ac0.y);
        ac0.z = fmaf(x0.z, w2.z, ac0.z); ac0.w = fmaf(x0.z, w2.w, ac0.w);
        ac0.x = fmaf(x0.w, w3.x, ac0.x); ac0.y = fmaf(x0.w, w3.y, ac0.y);
        ac0.z = fmaf(x0.w, w3.z, ac0.z); ac0.w = fmaf(x0.w, w3.w, ac0.w);
        ac1.x = fmaf(x1.x, w0.x, ac1.x); ac1.y = fmaf(x1.x, w0.y, ac1.y);
        ac1.z = fmaf(x1.x, w0.z, ac1.z); ac1.w = fmaf(x1.x, w0.w, ac1.w);
        ac1.x = fmaf(x1.y, w1.x, ac1.x); ac1.y = fmaf(x1.y, w1.y, ac1.y);
        ac1.z = fmaf(x1.y, w1.z, ac1.z); ac1.w = fmaf(x1.y, w1.w, ac1.w);
        ac1.x = fmaf(x1.z, w2.x, ac1.x); ac1.y = fmaf(x1.z, w2.y, ac1.y);
        ac1.z = fmaf(x1.z, w2.z, ac1.z); ac1.w = fmaf(x1.z, w2.w, ac1.w);
        ac1.x = fmaf(x1.w, w3.x, ac1.x); ac1.y = fmaf(x1.w, w3.y, ac1.y);
        ac1.z = fmaf(x1.w, w3.z, ac1.z); ac1.w = fmaf(x1.w, w3.w, ac1.w);
    }
    if (node0 < n) {
        union { __half2 h[2]; uint2 u; } pk;
        pk.h[0] = __floats2half2_rn(ac0.x, ac0.y);
        pk.h[1] = __floats2half2_rn(ac0.z, ac0.w);
        g_h[node0 * 8 + w] = pk.u;
    }
    if (node1 < n) {
        union { __half2 h[2]; uint2 u; } pk;
        pk.h[0] = __floats2half2_rn(ac1.x, ac1.y);
        pk.h[1] = __floats2half2_rn(ac1.z, ac1.w);
        g_h[node1 * 8 + w] = pk.u;
    }

    sm_ps[w][lane]      = ac0.x * s_as[w * 4]     + ac0.y * s_as[w * 4 + 1]
                        + ac0.z * s_as[w * 4 + 2] + ac0.w * s_as[w * 4 + 3];
    sm_pd[w][lane]      = ac0.x * s_ad[w * 4]     + ac0.y * s_ad[w * 4 + 1]
                        + ac0.z * s_ad[w * 4 + 2] + ac0.w * s_ad[w * 4 + 3];
    sm_ps[w][lane + 32] = ac1.x * s_as[w * 4]     + ac1.y * s_as[w * 4 + 1]
                        + ac1.z * s_as[w * 4 + 2] + ac1.w * s_as[w * 4 + 3];
    sm_pd[w][lane + 32] = ac1.x * s_ad[w * 4]     + ac1.y * s_ad[w * 4 + 1]
                        + ac1.z * s_ad[w * 4 + 2] + ac1.w * s_ad[w * 4 + 3];
    __syncthreads();
    if (tid < 128) {
        int l = tid & 63, hh = tid >> 6;
        int node2 = nb + l;
        if (node2 < n) {
            int wb = hh * 4;
            float vs = sm_ps[wb][l] + sm_ps[wb + 1][l] + sm_ps[wb + 2][l] + sm_ps[wb + 3][l];
            float vd = sm_pd[wb][l] + sm_pd[wb + 1][l] + sm_pd[wb + 2][l] + sm_pd[wb + 3][l];
            g_asrc[node2 * 2 + hh] = vs;
            g_adst[node2 * 2 + hh] = vd;
        }
    }
}

// ---------------------------------------------------------------------------
// fused aggregation: warp per dst node; 4 edges per gather iteration
// (four 8-lane groups); fp16 feature rows decoded to fp32 for accumulation.
// LAYER==0: features g_h/asrc/adst; epilogue = layer-2 transform -> g_out.
// LAYER==1: features g_out/asrc2/adst2; epilogue = mean-pool accumulation.
template <int LAYER>
__global__ void __launch_bounds__(256, 6)
k_agg(int n,
      const float* __restrict__ W2, const float* __restrict__ b1,
      const float* __restrict__ as2, const float* __restrict__ ad2,
      const int* __restrict__ batch, const float* __restrict__ b2,
      int G) {
    __shared__ float4 stage[8][32];
    __shared__ float W2s[32 * 32];
    __shared__ float b1s[32], as2s[32], ad2s[32];
    int tid = threadIdx.x;
    if (LAYER == 0) {
        for (int i = tid; i < 1024; i += 256) W2s[i] = W2[i];
        if (tid < 32) {
            b1s[tid] = b1[tid];
            as2s[tid] = as2[tid];
            ad2s[tid] = ad2[tid];
        }
        __syncthreads();
    }

    int wg = (blockIdx.x * blockDim.x + tid) >> 5;
    if (wg >= n) return;
    int w = tid >> 5, lane = tid & 31;
    int grp = lane >> 3;           // 4 groups of 8 lanes; group g takes edge t+g
    int q = lane & 7;              // lane-in-group owns columns 4q..4q+3
    int node = wg;
    float c0 = g_scal[2 + LAYER * 2];
    float c1 = g_scal[3 + LAYER * 2];
    float mean = g_scal[1];
    const uint2*  hf8  = LAYER ? g_out   : g_h;
    const float*  asrc = LAYER ? g_asrc2 : g_asrc;
    const float*  adst = LAYER ? g_adst2 : g_adst;
    float2 ad = ((const float2*)adst)[node];
    bool head1 = q >= 4;           // column quad's head (cols 16..31 -> head 1)

    float4 acc = make_float4(0.f, 0.f, 0.f, 0.f);
    float s0 = 0.f, s1 = 0.f;
    int beg = g_rowptr[node], end = g_rowptr[node + 1];

    for (int j0 = beg; j0 < end; j0 += 32) {
        int j = j0 + lane;
        bool v = j < end;
        int src = node;
        float av = 0.f;
        if (v) {
            int2 p = g_csr[j];
            src = p.x;
            av = __int_as_float(p.y);
        }
        float2 as = ((const float2*)asrc)[src];
        float a0 = as.x + ad.x + av * c0;
        float a1 = as.y + ad.y + av * c1;
        a0 = a0 > 0.f ? a0 : 0.2f * a0;
        a1 = a1 > 0.f ? a1 : 0.2f * a1;
        float ex0 = v ? __expf(a0) : 0.f;   // invalid lanes stage ex=0
        float ex1 = v ? __expf(a1) : 0.f;
        s0 += ex0;
        s1 += ex1;
        stage[w][lane] = make_float4(__int_as_float(src), ex0, ex1, 0.f);
        __syncwarp();
        int cnt = min(end - j0, 32);
        if (cnt == 32) {
            #pragma unroll
            for (int t = 0; t < 32; t += 4) {
                float4 p = stage[w][t + grp];
                union { uint2 u; __half2 h[2]; } pk;
                pk.u = hf8[__float_as_int(p.x) * 8 + q];   // 64B row per edge
                float2 f01 = __half22float2(pk.h[0]);
                float2 f23 = __half22float2(pk.h[1]);
                float e = head1 ? p.z : p.y;
                acc.x = fmaf(f01.x, e, acc.x);
                acc.y = fmaf(f01.y, e, acc.y);
                acc.z = fmaf(f23.x, e, acc.z);
                acc.w = fmaf(f23.y, e, acc.w);
            }
        } else {
            for (int t = 0; t < cnt; t += 4) {            // slots >= cnt carry ex=0
                float4 p = stage[w][t + grp];
                union { uint2 u; __half2 h[2]; } pk;
                pk.u = hf8[__float_as_int(p.x) * 8 + q];
                float2 f01 = __half22float2(pk.h[0]);
                float2 f23 = __half22float2(pk.h[1]);
                float e = head1 ? p.z : p.y;
                acc.x = fmaf(f01.x, e, acc.x);
                acc.y = fmaf(f01.y, e, acc.y);
                acc.z = fmaf(f23.x, e, acc.z);
                acc.w = fmaf(f23.y, e, acc.w);
            }
        }
        __syncwarp();
    }

    // combine the 4 groups (lanes q, q+8, q+16, q+24 hold the same columns)
    acc.x += __shfl_down_sync(0xffffffffu, acc.x, 16);
    acc.y += __shfl_down_sync(0xffffffffu, acc.y, 16);
    acc.z += __shfl_down_sync(0xffffffffu, acc.z, 16);
    acc.w += __shfl_down_sync(0xffffffffu, acc.w, 16);
    acc.x += __shfl_down_sync(0xffffffffu, acc.x, 8);
    acc.y += __shfl_down_sync(0xffffffffu, acc.y, 8);
    acc.z += __shfl_down_sync(0xffffffffu, acc.z, 8);
    acc.w += __shfl_down_sync(0xffffffffu, acc.w, 8);

    // self loop (src = node, ea = mean): add in lanes 0-7 after combine
    {
        float2 as = ((const float2*)asrc)[node];
        float a0 = as.x + ad.x + mean * c0;
        float a1 = as.y + ad.y + mean * c1;
        a0 = a0 > 0.f ? a0 : 0.2f * a0;
        a1 = a1 > 0.f ? a1 : 0.2f * a1;
        float ex0 = __expf(a0), ex1 = __expf(a1);
        if (lane == 0) { s0 += ex0; s1 += ex1; }
        union { uint2 u; __half2 h[2]; } pk;
        pk.u = hf8[node * 8 + q];
        float2 f01 = __half22float2(pk.h[0]);
        float2 f23 = __half22float2(pk.h[1]);
        float e = (lane < 8) ? (head1 ? ex1 : ex0) : 0.f;
        acc.x = fmaf(f01.x, e, acc.x);
        acc.y = fmaf(f01.y, e, acc.y);
        acc.z = fmaf(f23.x, e, acc.z);
        acc.w = fmaf(f23.y, e, acc.w);
    }

    #pragma unroll
    for (int off = 16; off; off >>= 1) {
        s0 += __shfl_xor_sync(0xffffffffu, s0, off);
        s1 += __shfl_xor_sync(0xffffffffu, s1, off);
    }
    float sinv = 1.f / ((head1 ? s1 : s0) + 1e-16f);
    float4 o4 = make_float4(acc.x * sinv, acc.y * sinv, acc.z * sinv, acc.w * sinv);
    // o4 valid in lanes 0-7 (columns 4q..4q+3)

    if (LAYER == 0) {
        // fused layer-2 transform: x2 = relu(o + b1); h2 = x2 @ W2 (fp32 math)
        float* xrow = (float*)&stage[w][0];
        if (lane < 8) {
            xrow[4 * q]     = fmaxf(o4.x + b1s[4 * q], 0.f);
            xrow[4 * q + 1] = fmaxf(o4.y + b1s[4 * q + 1], 0.f);
            xrow[4 * q + 2] = fmaxf(o4.z + b1s[4 * q + 2], 0.f);
            xrow[4 * q + 3] = fmaxf(o4.w + b1s[4 * q + 3], 0.f);
        }
        __syncwarp();
        float acc2 = 0.f;
        #pragma unroll 8
        for (int k = 0; k < 32; k++)
            acc2 = fmaf(xrow[k], W2s[k * 32 + lane], acc2);
        // store h2 row as fp16 (pairs from even lanes)
        float nbv = __shfl_down_sync(0xffffffffu, acc2, 1);
        if ((lane & 1) == 0) {
            __half2 hv = __floats2half2_rn(acc2, nbv);
            ((unsigned*)g_out)[node * 16 + (lane >> 1)] = *(unsigned*)&hv;
        }
        float ps = acc2 * as2s[lane];
        float pd = acc2 * ad2s[lane];
        #pragma unroll
        for (int off = 8; off; off >>= 1) {
            ps += __shfl_down_sync(0xffffffffu, ps, off, 16);
            pd += __shfl_down_sync(0xffffffffu, pd, off, 16);
        }
        if ((lane & 15) == 0) {
            int hh = lane >> 4;
            g_asrc2[node * 2 + hh] = ps;
            g_adst2[node * 2 + hh] = pd;
        }
    } else {
        int g = clampi(batch[node], G);
        if (lane < 8) {
            float4 add = make_float4(o4.x + b2[4 * q],     o4.y + b2[4 * q + 1],
                                     o4.z + b2[4 * q + 2], o4.w + b2[4 * q + 3]);
            atomicAdd((float4*)&g_pool[g * 32 + 4 * q], add);
        }
        if (lane == 0) atomicAdd(&g_cnt[g], 1.f);
    }
}

// ---------------------------------------------------------------------------
// MLP head + accumulator cleanup for the next pipeline pass.
__global__ void k_mlp(float* __restrict__ out,
                      const float* __restrict__ Wf1, const float* __restrict__ bf1,
                      const float* __restrict__ Wf2, const float* __restrict__ bf2, int G) {
    int g = blockIdx.x * blockDim.x + threadIdx.x;
    if (g >= G) return;
    float cnt = g_cnt[g];
    float inv = 1.f / fmaxf(cnt, 1.f);
    float emb[32];
    #pragma unroll
    for (int i = 0; i < 32; i++) {
        emb[i] = g_pool[g * 32 + i] * inv;
        g_pool[g * 32 + i] = 0.f;        // restore for next replay
    }
    g_cnt[g] = 0.f;
    if (g == 0) g_scal[0] = 0.f;
    float o0 = bf2[0], o1 = bf2[1];
    for (int j = 0; j < 32; j++) {
        float z = bf1[j];
        #pragma unroll
        for (int i = 0; i < 32; i++) z = fmaf(emb[i], Wf1[i * 32 + j], z);
        z = fmaxf(z, 0.f);
        o0 = fmaf(z, Wf2[j * 2], o0);
        o1 = fmaf(z, Wf2[j * 2 + 1], o1);
    }
    out[g * 2] = o0;
    out[g * 2 + 1] = o1;
}

// ---------------------------------------------------------------------------
extern "C" void kernel_launch(void* const* d_in, const int* in_sizes, int n_in,
                              void* d_out, int out_size) {
    const float* x     = (const float*)d_in[0];
    const int*   ei    = (const int*)d_in[1];
    const float* ea    = (const float*)d_in[2];
    const int*   batch = (const int*)d_in[3];
    const float* W1  = (const float*)d_in[4];
    const float* as1 = (const float*)d_in[5];
    const float* ad1 = (const float*)d_in[6];
    const float* We1 = (const float*)d_in[7];
    const float* ae1 = (const float*)d_in[8];
    const float* b1  = (const float*)d_in[9];
    const float* W2  = (const float*)d_in[10];
    const float* as2 = (const float*)d_in[11];
    const float* ad2 = (const float*)d_in[12];
    const float* We2 = (const float*)d_in[13];
    const float* ae2 = (const float*)d_in[14];
    const float* b2  = (const float*)d_in[15];
    const float* Wf1 = (const float*)d_in[16];
    const float* bf1 = (const float*)d_in[17];
    const float* Wf2 = (const float*)d_in[18];
    const float* bf2 = (const float*)d_in[19];

    int N = in_sizes[0] / 128;
    int E = in_sizes[1] / 2;
    int G = out_size / 2;
    int nb = (N + 1023) / 1024;
    int tb = (N + 63) / 64;           // transform blocks (64 nodes each)
    int ab = (N + 7) / 8;

    // 1: vectorized histogram + esum
    k_hist<<<2048, 512>>>(ei, ea, E, N);
    // 2: single-launch scan (rowptr + cursor, folded prep, deg re-zero)
    k_scanL<<<nb, 1024>>>(N, E, We1, ae1, We2, ae2);
    // 3: 4x-unrolled cursor-atomic scatter (+ flag reset)
    k_scatter<<<1024, 512>>>(ei, ea, E, N);
    // 4: 64-node layer-1 transform  <- ncu capture slot
    k_transform1<<<tb, 256>>>(x, W1, as1, ad1, N);
    // 5: agg0 (fused layer-2 transform epilogue)
    k_agg<0><<<ab, 256>>>(N, W2, b1, as2, ad2, nullptr, nullptr, G);
    // 6: agg1 (fused mean-pool)
    k_agg<1><<<ab, 256>>>(N, nullptr, nullptr, nullptr, nullptr, batch, b2, G);
    // 7: MLP head (+ accumulator cleanup)
    k_mlp<<<1, 64>>>((float*)d_out, Wf1, bf1, Wf2, bf2, G);
}